// round 10
// baseline (speedup 1.0000x reference)
#include <cuda_runtime.h>
#include <cstdint>

#define KSZ 5
#define NBUCKETS 25
#define BATCH 8
#define CHANNELS 96
#define HEIGHT 192
#define WIDTH 192

#define BTX 16
#define BTY 8
#define NTHREADS (BTX*BTY)   // 128
#define PX 4
#define CH 2
#define NBUF 4
#define TILE_OW (BTX*PX)  // 64
#define TILE_OH BTY       // 8
#define HALO 2
#define TROWS (TILE_OH + 2*HALO)   // 12
#define TCOLS (TILE_OW + 2*HALO)   // 68
#define TSTRIDE 72                 // floats per row (16B-aligned)
#define TILE_FLOATS (TROWS * TSTRIDE)
#define NPAIRS (TROWS * (TCOLS/2))  // 12*34 = 408 8-byte pairs
#define NITER (CHANNELS / CH)       // 48
#define NSLOT 4                     // ceil(408/128)

__device__ __forceinline__ void cp_async8(uint32_t smem_dst, const void* gptr, int src_bytes) {
    asm volatile("cp.async.ca.shared.global [%0], [%1], 8, %2;\n"
                 :: "r"(smem_dst), "l"(gptr), "r"(src_bytes));
}
__device__ __forceinline__ void cp_async_commit() {
    asm volatile("cp.async.commit_group;\n" ::: "memory");
}
template <int N>
__device__ __forceinline__ void cp_async_wait() {
    asm volatile("cp.async.wait_group %0;\n" :: "n"(N) : "memory");
}

__global__ __launch_bounds__(NTHREADS, 4) void csconv2d_kernel(
    const float* __restrict__ input,        // [B,C,H,W]
    const float* __restrict__ kernel_bank,  // [25,5,5]
    const int* __restrict__ buckets,        // [B,H,W] int32
    float* __restrict__ output)             // [B,C,H,W]
{
    __shared__ __align__(16) float s_tile[NBUF][CH][TILE_FLOATS];  // 27.6 KB
    __shared__ __align__(16) float s_bank[640];

    const int tx = threadIdx.x;
    const int ty = threadIdx.y;
    const int tid = ty * BTX + tx;

    const int w0 = blockIdx.x * TILE_OW;
    const int h0 = blockIdx.y * TILE_OH;
    const int b  = blockIdx.z;

    const int h = h0 + ty;
    const int wbase = w0 + PX * tx;

    for (int i = tid; i < NBUCKETS * KSZ * KSZ; i += NTHREADS)
        s_bank[i] = kernel_bank[i];
    __syncthreads();

    const int4 bk4 = *reinterpret_cast<const int4*>(
        &buckets[((long long)b * HEIGHT + h) * WIDTH + wbase]);
    int bkt[PX] = {bk4.x, bk4.y, bk4.z, bk4.w};
    #pragma unroll
    for (int p = 0; p < PX; p++)
        bkt[p] = min(max(bkt[p], 0), NBUCKETS - 1);

    float wk[PX * 25];
    #pragma unroll
    for (int p = 0; p < PX; p++)
        #pragma unroll
        for (int t = 0; t < 25; t++)
            wk[p * 25 + t] = s_bank[bkt[p] * 25 + t];

    const float* inb  = input  + (size_t)b * CHANNELS * HEIGHT * WIDTH;
    float*       outb = output + (size_t)b * CHANNELS * HEIGHT * WIDTH;

    const uint32_t s_tile_base = (uint32_t)__cvta_generic_to_shared(&s_tile[0][0][0]);

    // Iteration-invariant fill slots.
    int      g_rel[NSLOT];
    uint32_t s_rel[NSLOT];
    int      nbytes[NSLOT];
    #pragma unroll
    for (int s = 0; s < NSLOT; s++) {
        const int idx = tid + s * NTHREADS;
        if (idx < NPAIRS) {
            const int r   = idx / (TCOLS / 2);
            const int col = (idx % (TCOLS / 2)) * 2;
            const int gh = h0 + r - HALO;
            const int gw = w0 + col - HALO;
            const bool ok = ((unsigned)gh < HEIGHT) & ((unsigned)gw < WIDTH);
            g_rel[s]  = ok ? (gh * WIDTH + gw) : 0;
            s_rel[s]  = (uint32_t)((r * TSTRIDE + col) * 4);
            nbytes[s] = ok ? 8 : 0;
        } else {
            g_rel[s] = 0; s_rel[s] = 0; nbytes[s] = -1;
        }
    }

    auto issue_pair = [&](int c0, int buf) {
        #pragma unroll
        for (int cc = 0; cc < CH; cc++) {
            const float* chan = inb + (size_t)(c0 + cc) * (HEIGHT * WIDTH);
            const uint32_t sbase = s_tile_base
                + (uint32_t)((buf * CH + cc) * TILE_FLOATS * 4);
            #pragma unroll
            for (int s = 0; s < NSLOT; s++)
                if (nbytes[s] >= 0)
                    cp_async8(sbase + s_rel[s], chan + g_rel[s], nbytes[s]);
        }
        cp_async_commit();
    };

    // Prologue: 3 groups in flight.
    issue_pair(0, 0);
    issue_pair(CH, 1);
    issue_pair(2 * CH, 2);

    #pragma unroll 1
    for (int it = 0; it < NITER; it++) {
        const int buf = it & (NBUF - 1);
        const int c0 = it * CH;

        const int rem = (NITER - 1) - it;
        if (rem >= 2)      cp_async_wait<2>();
        else if (rem == 1) cp_async_wait<1>();
        else               cp_async_wait<0>();
        __syncthreads();

        if (it + 3 < NITER)
            issue_pair(c0 + 3 * CH, (it + 3) & (NBUF - 1));

        float acc[CH][PX];
        #pragma unroll
        for (int cc = 0; cc < CH; cc++)
            #pragma unroll
            for (int p = 0; p < PX; p++) acc[cc][p] = 0.f;

        #pragma unroll
        for (int i = 0; i < KSZ; i++) {
            #pragma unroll
            for (int cc = 0; cc < CH; cc++) {
                const float* row = &s_tile[buf][cc][(ty + i) * TSTRIDE + PX * tx];
                const float4 a  = *reinterpret_cast<const float4*>(row);
                const float4 bq = *reinterpret_cast<const float4*>(row + 4);
                const float v[8] = {a.x, a.y, a.z, a.w, bq.x, bq.y, bq.z, bq.w};
                #pragma unroll
                for (int p = 0; p < PX; p++)
                    #pragma unroll
                    for (int j = 0; j < KSZ; j++)
                        acc[cc][p] = fmaf(v[p + j], wk[p * 25 + i * KSZ + j], acc[cc][p]);
            }
        }

        #pragma unroll
        for (int cc = 0; cc < CH; cc++) {
            float4 o = {acc[cc][0], acc[cc][1], acc[cc][2], acc[cc][3]};
            *reinterpret_cast<float4*>(
                &outb[((size_t)(c0 + cc) * HEIGHT + h) * WIDTH + wbase]) = o;
        }
    }
}

extern "C" void kernel_launch(void* const* d_in, const int* in_sizes, int n_in,
                              void* d_out, int out_size)
{
    const float* input       = (const float*)d_in[0];
    const float* kernel_bank = (const float*)d_in[1];
    const int*   buckets     = (const int*)d_in[2];
    float*       output      = (float*)d_out;

    dim3 block(BTX, BTY, 1);
    dim3 grid(WIDTH / TILE_OW, HEIGHT / TILE_OH, BATCH);   // (3, 24, 8)
    csconv2d_kernel<<<grid, block>>>(input, kernel_bank, buckets, output);
}

// round 11
// speedup vs baseline: 1.1051x; 1.1051x over previous
#include <cuda_runtime.h>
#include <cstdint>

#define KSZ 5
#define NBUCKETS 25
#define BATCH 8
#define CHANNELS 96
#define HEIGHT 192
#define WIDTH 192

#define BTX 16
#define BTY 16
#define NTHREADS (BTX*BTY)   // 256
#define PX 2
#define CH 2
#define NBUF 4
#define TILE_OW (BTX*PX)  // 32
#define TILE_OH BTY       // 16
#define HALO 2
#define TROWS (TILE_OH + 2*HALO)   // 20
#define TCOLS (TILE_OW + 2*HALO)   // 36
#define TSTRIDE 40                 // floats per row (160B, 16B multiple)
#define TILE_FLOATS (TROWS * TSTRIDE)   // 800
#define NPAIRS (TROWS * (TCOLS/2))  // 20*18 = 360 8-byte pairs
#define NITER (CHANNELS / CH)       // 48
#define NSLOT 2                     // ceil(360/256)

__device__ __forceinline__ void cp_async8(uint32_t smem_dst, const void* gptr, int src_bytes) {
    asm volatile("cp.async.ca.shared.global [%0], [%1], 8, %2;\n"
                 :: "r"(smem_dst), "l"(gptr), "r"(src_bytes));
}
__device__ __forceinline__ void cp_async_commit() {
    asm volatile("cp.async.commit_group;\n" ::: "memory");
}
template <int N>
__device__ __forceinline__ void cp_async_wait() {
    asm volatile("cp.async.wait_group %0;\n" :: "n"(N) : "memory");
}

__global__ __launch_bounds__(NTHREADS, 3) void csconv2d_kernel(
    const float* __restrict__ input,        // [B,C,H,W]
    const float* __restrict__ kernel_bank,  // [25,5,5]
    const int* __restrict__ buckets,        // [B,H,W] int32
    float* __restrict__ output)             // [B,C,H,W]
{
    __shared__ __align__(16) float s_tile[NBUF][CH][TILE_FLOATS];  // 25.6 KB
    __shared__ __align__(16) float s_bank[640];

    const int tx = threadIdx.x;
    const int ty = threadIdx.y;
    const int tid = ty * BTX + tx;

    const int w0 = blockIdx.x * TILE_OW;
    const int h0 = blockIdx.y * TILE_OH;
    const int b  = blockIdx.z;

    const int h = h0 + ty;
    const int wbase = w0 + PX * tx;    // even

    for (int i = tid; i < NBUCKETS * KSZ * KSZ; i += NTHREADS)
        s_bank[i] = kernel_bank[i];
    __syncthreads();

    const int2 bk2 = *reinterpret_cast<const int2*>(
        &buckets[((long long)b * HEIGHT + h) * WIDTH + wbase]);
    int bkt[PX] = {bk2.x, bk2.y};
    #pragma unroll
    for (int p = 0; p < PX; p++)
        bkt[p] = min(max(bkt[p], 0), NBUCKETS - 1);

    // 50 weight registers: 25 per pixel, reused across all 96 channels.
    float wk[PX * 25];
    #pragma unroll
    for (int p = 0; p < PX; p++)
        #pragma unroll
        for (int t = 0; t < 25; t++)
            wk[p * 25 + t] = s_bank[bkt[p] * 25 + t];

    const float* inb  = input  + (size_t)b * CHANNELS * HEIGHT * WIDTH;
    float*       outb = output + (size_t)b * CHANNELS * HEIGHT * WIDTH;

    const uint32_t s_tile_base = (uint32_t)__cvta_generic_to_shared(&s_tile[0][0][0]);

    // Iteration-invariant fill slots (8-byte pairs; pairs start even, never
    // straddle the W=192 boundary; zfill for OOB).
    int      g_rel[NSLOT];
    uint32_t s_rel[NSLOT];
    int      nbytes[NSLOT];
    #pragma unroll
    for (int s = 0; s < NSLOT; s++) {
        const int idx = tid + s * NTHREADS;
        if (idx < NPAIRS) {
            const int r   = idx / (TCOLS / 2);
            const int col = (idx % (TCOLS / 2)) * 2;
            const int gh = h0 + r - HALO;
            const int gw = w0 + col - HALO;
            const bool ok = ((unsigned)gh < HEIGHT) & ((unsigned)gw < WIDTH);
            g_rel[s]  = ok ? (gh * WIDTH + gw) : 0;
            s_rel[s]  = (uint32_t)((r * TSTRIDE + col) * 4);
            nbytes[s] = ok ? 8 : 0;
        } else {
            g_rel[s] = 0; s_rel[s] = 0; nbytes[s] = -1;
        }
    }

    auto issue_pair = [&](int c0, int buf) {
        #pragma unroll
        for (int cc = 0; cc < CH; cc++) {
            const float* chan = inb + (size_t)(c0 + cc) * (HEIGHT * WIDTH);
            const uint32_t sbase = s_tile_base
                + (uint32_t)((buf * CH + cc) * TILE_FLOATS * 4);
            #pragma unroll
            for (int s = 0; s < NSLOT; s++)
                if (nbytes[s] >= 0)
                    cp_async8(sbase + s_rel[s], chan + g_rel[s], nbytes[s]);
        }
        cp_async_commit();
    };

    // Prologue: 3 groups in flight.
    issue_pair(0, 0);
    issue_pair(CH, 1);
    issue_pair(2 * CH, 2);

    #pragma unroll 1
    for (int it = 0; it < NITER; it++) {
        const int buf = it & (NBUF - 1);
        const int c0 = it * CH;

        const int rem = (NITER - 1) - it;
        if (rem >= 2)      cp_async_wait<2>();
        else if (rem == 1) cp_async_wait<1>();
        else               cp_async_wait<0>();
        __syncthreads();

        if (it + 3 < NITER)
            issue_pair(c0 + 3 * CH, (it + 3) & (NBUF - 1));

        float acc[CH][PX];
        #pragma unroll
        for (int cc = 0; cc < CH; cc++)
            #pragma unroll
            for (int p = 0; p < PX; p++) acc[cc][p] = 0.f;

        #pragma unroll
        for (int i = 0; i < KSZ; i++) {
            #pragma unroll
            for (int cc = 0; cc < CH; cc++) {
                // Window cols 2tx .. 2tx+5 (tile col 0 = w0-2): three aligned LDS.64.
                const float* row = &s_tile[buf][cc][(ty + i) * TSTRIDE + PX * tx];
                const float2 q0 = *reinterpret_cast<const float2*>(row);
                const float2 q1 = *reinterpret_cast<const float2*>(row + 2);
                const float2 q2 = *reinterpret_cast<const float2*>(row + 4);
                const float v[6] = {q0.x, q0.y, q1.x, q1.y, q2.x, q2.y};
                #pragma unroll
                for (int p = 0; p < PX; p++)
                    #pragma unroll
                    for (int j = 0; j < KSZ; j++)
                        acc[cc][p] = fmaf(v[p + j], wk[p * 25 + i * KSZ + j], acc[cc][p]);
            }
        }

        #pragma unroll
        for (int cc = 0; cc < CH; cc++) {
            float2 o = {acc[cc][0], acc[cc][1]};
            *reinterpret_cast<float2*>(
                &outb[((size_t)(c0 + cc) * HEIGHT + h) * WIDTH + wbase]) = o;
        }
    }
}

extern "C" void kernel_launch(void* const* d_in, const int* in_sizes, int n_in,
                              void* d_out, int out_size)
{
    const float* input       = (const float*)d_in[0];
    const float* kernel_bank = (const float*)d_in[1];
    const int*   buckets     = (const int*)d_in[2];
    float*       output      = (float*)d_out;

    dim3 block(BTX, BTY, 1);
    dim3 grid(WIDTH / TILE_OW, HEIGHT / TILE_OH, BATCH);   // (6, 12, 8)
    csconv2d_kernel<<<grid, block>>>(input, kernel_bank, buckets, output);
}